// round 14
// baseline (speedup 1.0000x reference)
#include <cuda_runtime.h>

typedef unsigned long long u64;

#define TPB   512
#define NCOL  4096
#define VPT   8       // elements per thread (4096 / 512)
#define NPAIR 4
#define NWARP 16
#define KITER 16

// ---- packed f32x2 helpers (ptxas never auto-fuses these from C++) ----
__device__ __forceinline__ u64 pk2(float a, float b) {
    u64 r; asm("mov.b64 %0,{%1,%2};" : "=l"(r) : "f"(a), "f"(b)); return r;
}
__device__ __forceinline__ void upk2(u64 v, float& a, float& b) {
    asm("mov.b64 {%0,%1},%2;" : "=f"(a), "=f"(b) : "l"(v));
}
__device__ __forceinline__ u64 mul2(u64 a, u64 b) {
    u64 d; asm("mul.rn.f32x2 %0,%1,%2;" : "=l"(d) : "l"(a), "l"(b)); return d;
}
__device__ __forceinline__ u64 add2(u64 a, u64 b) {
    u64 d; asm("add.rn.f32x2 %0,%1,%2;" : "=l"(d) : "l"(a), "l"(b)); return d;
}
__device__ __forceinline__ u64 fma2(u64 a, u64 b, u64 c) {
    u64 d; asm("fma.rn.f32x2 %0,%1,%2,%3;" : "=l"(d) : "l"(a), "l"(b), "l"(c)); return d;
}
__device__ __forceinline__ float rcpf(float x) {
    float r; asm("rcp.approx.f32 %0,%1;" : "=f"(r) : "f"(x)); return r;
}

// One CTA (512 threads, 16 warps) per row of 4096; VPT=8 -> w2[4]+kn2[4] is
// only 16 registers of live state, targeting 4 CTAs/SM (100% occupancy).
// Per iteration:
//   S = block_sum(w); ninv = -1/S
//   noh = w*ninv (= -onehot); kn += noh (accumulates -khot); w = fma(noh, w, w)
// Final store negates kn. Reduction: packed tree (3 adds) -> 5-shfl full-warp
// reduce -> 16 smem partials -> 1 barrier -> 4 broadcast float4 + packed tree.
__global__ __launch_bounds__(TPB, 4) void subset_op_kernel(
    const float* __restrict__ scores, const float* __restrict__ g,
    float* __restrict__ out)
{
    __shared__ __align__(16) float red_max[NWARP];
    __shared__ __align__(16) float red_sum[2][NWARP];

    const int tid  = threadIdx.x;
    const int lane = tid & 31;
    const int wid  = tid >> 5;
    const size_t base = (size_t)blockIdx.x * NCOL;

    const float4* sc4 = reinterpret_cast<const float4*>(scores + base);
    const float4* g4  = reinterpret_cast<const float4*>(g + base);

    // ---- load + perturb: s = scores + g (coalesced float4, 2 per thread) ----
    float s[VPT];
    #pragma unroll
    for (int j = 0; j < 2; j++) {
        float4 a = sc4[j * TPB + tid];
        float4 b = g4 [j * TPB + tid];
        s[4*j+0] = a.x + b.x; s[4*j+1] = a.y + b.y;
        s[4*j+2] = a.z + b.z; s[4*j+3] = a.w + b.w;
    }

    // ---- block max (one-time) ----
    float m = s[0];
    #pragma unroll
    for (int i = 1; i < VPT; i++) m = fmaxf(m, s[i]);
    #pragma unroll
    for (int o = 16; o > 0; o >>= 1)
        m = fmaxf(m, __shfl_xor_sync(0xffffffffu, m, o));
    if (lane == 0) red_max[wid] = m;
    __syncthreads();
    #pragma unroll
    for (int j = 0; j < 4; j++) {
        float4 r = *reinterpret_cast<const float4*>(&red_max[4 * j]);
        m = fmaxf(m, fmaxf(fmaxf(r.x, r.y), fmaxf(r.z, r.w)));
    }

    // ---- w = exp(s - m): the ONLY transcendental; kn accumulates -khot ----
    u64 w2[NPAIR], kn2[NPAIR];
    #pragma unroll
    for (int p = 0; p < NPAIR; p++) {
        w2[p]  = pk2(__expf(s[2*p] - m), __expf(s[2*p+1] - m));
        kn2[p] = pk2(0.f, 0.f);
    }

    // ---- block sum of w -> ninv2 = {-1/S, -1/S}; 1 barrier per iteration ----
    auto block_ninv = [&](int it) -> u64 {
        // intra-thread packed tree (3 adds, depth 2)
        u64 a0 = add2(w2[0], w2[1]);
        u64 a1 = add2(w2[2], w2[3]);
        a0 = add2(a0, a1);
        float lo, hi; upk2(a0, lo, hi);
        float local = lo + hi;
        #pragma unroll
        for (int o = 16; o > 0; o >>= 1)
            local += __shfl_xor_sync(0xffffffffu, local, o);
        if (lane == 0) red_sum[it & 1][wid] = local;
        __syncthreads();
        // broadcast read of 16 partials, packed-summed (identical in all threads)
        const float* rs = red_sum[it & 1];
        float4 r0 = *reinterpret_cast<const float4*>(&rs[0]);
        float4 r1 = *reinterpret_cast<const float4*>(&rs[4]);
        float4 r2 = *reinterpret_cast<const float4*>(&rs[8]);
        float4 r3 = *reinterpret_cast<const float4*>(&rs[12]);
        u64 t0 = add2(pk2(r0.x, r0.y), pk2(r0.z, r0.w));
        u64 t1 = add2(pk2(r1.x, r1.y), pk2(r1.z, r1.w));
        u64 t2 = add2(pk2(r2.x, r2.y), pk2(r2.z, r2.w));
        u64 t3 = add2(pk2(r3.x, r3.y), pk2(r3.z, r3.w));
        t0 = add2(add2(t0, t1), add2(t2, t3));
        float sl, sh; upk2(t0, sl, sh);
        float ninv = rcpf(sl + sh);
        return pk2(-ninv, -ninv);
    };

    for (int it = 0; it < KITER - 1; it++) {
        u64 ninv2 = block_ninv(it);
        #pragma unroll
        for (int p = 0; p < NPAIR; p++) {
            u64 noh = mul2(w2[p], ninv2);        // -onehot
            w2[p]   = fma2(noh, w2[p], w2[p]);   // w *= (1 - onehot)  (critical path)
            kn2[p]  = add2(kn2[p], noh);         // -khot accumulation (off critical path)
        }
    }
    {   // last iteration: w update is dead
        u64 ninv2 = block_ninv(KITER - 1);
        #pragma unroll
        for (int p = 0; p < NPAIR; p++) {
            u64 noh = mul2(w2[p], ninv2);
            kn2[p]  = add2(kn2[p], noh);
        }
    }

    // ---- store khot = -kn (coalesced float4) ----
    float4* o4 = reinterpret_cast<float4*>(out + base);
    #pragma unroll
    for (int j = 0; j < 2; j++) {
        float4 v;
        float x0, x1, x2, x3;
        upk2(kn2[2*j],     x0, x1);
        upk2(kn2[2*j + 1], x2, x3);
        v.x = -x0; v.y = -x1; v.z = -x2; v.w = -x3;
        o4[j * TPB + tid] = v;
    }
}

extern "C" void kernel_launch(void* const* d_in, const int* in_sizes, int n_in,
                              void* d_out, int out_size) {
    const float* scores = (const float*)d_in[0];
    const float* g      = (const float*)d_in[1];
    float* out          = (float*)d_out;
    int rows = in_sizes[0] / NCOL;   // 4*2048 = 8192
    subset_op_kernel<<<rows, TPB>>>(scores, g, out);
}

// round 15
// speedup vs baseline: 1.5132x; 1.5132x over previous
#include <cuda_runtime.h>

typedef unsigned long long u64;

#define TPB   256
#define NCOL  4096
#define VPT   16      // elements per thread (4096 / 256)
#define NPAIR 8
#define NWARP 8
#define KITER 16      // 16 softmax iterations = 8 fused 2-iteration blocks

// ---- packed f32x2 helpers (ptxas never auto-fuses these from C++) ----
__device__ __forceinline__ u64 pk2(float a, float b) {
    u64 r; asm("mov.b64 %0,{%1,%2};" : "=l"(r) : "f"(a), "f"(b)); return r;
}
__device__ __forceinline__ void upk2(u64 v, float& a, float& b) {
    asm("mov.b64 {%0,%1},%2;" : "=f"(a), "=f"(b) : "l"(v));
}
__device__ __forceinline__ u64 mul2(u64 a, u64 b) {
    u64 d; asm("mul.rn.f32x2 %0,%1,%2;" : "=l"(d) : "l"(a), "l"(b)); return d;
}
__device__ __forceinline__ u64 add2(u64 a, u64 b) {
    u64 d; asm("add.rn.f32x2 %0,%1,%2;" : "=l"(d) : "l"(a), "l"(b)); return d;
}
__device__ __forceinline__ u64 fma2(u64 a, u64 b, u64 c) {
    u64 d; asm("fma.rn.f32x2 %0,%1,%2,%3;" : "=l"(d) : "l"(a), "l"(b), "l"(c)); return d;
}
__device__ __forceinline__ float rcpf(float x) {
    float r; asm("rcp.approx.f32 %0,%1;" : "=f"(r) : "f"(x)); return r;
}

// One CTA (256 threads) per row of 4096. w = exp(s - max) in registers,
// khot accumulated negated (kn). TWO softmax iterations per block reduction:
//   reduce (S, Q) = (sum w, sum w^2)  [packed together as f32x2 lanes]
//   ninv0 = -1/S;  S1 = S - Q/S  (exact algebraic next-iteration sum)
//   ninv1 = -1/S1
//   iter A: noh = w*ninv0; kn += noh; w = fma(noh, w, w)
//   iter B: noh = w*ninv1; kn += noh; w = fma(noh, w, w)
// -> 8 barriers instead of 16. S is bulk-dominated (~75), so Q/S^2 ~ 1% and
// the S-recurrence has no cancellation; rounding adds ~1e-7/iter, total ~1e-6.
__global__ __launch_bounds__(TPB, 5) void subset_op_kernel(
    const float* __restrict__ scores, const float* __restrict__ g,
    float* __restrict__ out)
{
    __shared__ float red_max[NWARP];
    __shared__ __align__(16) float2 red_sq[2][NWARP];   // (S, Q) per warp, parity buffered

    const int tid  = threadIdx.x;
    const int lane = tid & 31;
    const int wid  = tid >> 5;
    const size_t base = (size_t)blockIdx.x * NCOL;

    const float4* sc4 = reinterpret_cast<const float4*>(scores + base);
    const float4* g4  = reinterpret_cast<const float4*>(g + base);

    // ---- load + perturb: s = scores + g (coalesced float4) ----
    float s[VPT];
    #pragma unroll
    for (int j = 0; j < 4; j++) {
        float4 a = sc4[j * TPB + tid];
        float4 b = g4 [j * TPB + tid];
        s[4*j+0] = a.x + b.x; s[4*j+1] = a.y + b.y;
        s[4*j+2] = a.z + b.z; s[4*j+3] = a.w + b.w;
    }

    // ---- block max (one-time) ----
    float m = s[0];
    #pragma unroll
    for (int i = 1; i < VPT; i++) m = fmaxf(m, s[i]);
    #pragma unroll
    for (int o = 16; o > 0; o >>= 1)
        m = fmaxf(m, __shfl_xor_sync(0xffffffffu, m, o));
    if (lane == 0) red_max[wid] = m;
    __syncthreads();
    #pragma unroll
    for (int j = 0; j < NWARP; j++) m = fmaxf(m, red_max[j]);  // broadcast, identical everywhere

    // ---- w = exp(s - m): the ONLY transcendental; kn accumulates -khot ----
    u64 w2[NPAIR], kn2[NPAIR];
    #pragma unroll
    for (int p = 0; p < NPAIR; p++) {
        w2[p]  = pk2(__expf(s[2*p] - m), __expf(s[2*p+1] - m));
        kn2[p] = pk2(0.f, 0.f);
    }

    // ---- fused 2-iteration reduction: returns (ninv0, ninv1) packed ----
    auto block_ninv_pair = [&](int blk, float& ninv0, float& ninv1) {
        // partial S: packed tree (7 adds, depth 3)
        u64 a0 = add2(w2[0], w2[1]);
        u64 a1 = add2(w2[2], w2[3]);
        u64 a2 = add2(w2[4], w2[5]);
        u64 a3 = add2(w2[6], w2[7]);
        a0 = add2(a0, a1); a2 = add2(a2, a3);
        a0 = add2(a0, a2);
        float sl, sh; upk2(a0, sl, sh);
        float Sp = sl + sh;
        // partial Q = sum w^2: two fma chains (9 packed ops, depth 5)
        u64 q0 = mul2(w2[0], w2[0]);
        u64 q1 = mul2(w2[1], w2[1]);
        q0 = fma2(w2[2], w2[2], q0); q1 = fma2(w2[3], w2[3], q1);
        q0 = fma2(w2[4], w2[4], q0); q1 = fma2(w2[5], w2[5], q1);
        q0 = fma2(w2[6], w2[6], q0); q1 = fma2(w2[7], w2[7], q1);
        q0 = add2(q0, q1);
        float ql, qh; upk2(q0, ql, qh);
        float Qp = ql + qh;
        // two interleaved 5-shfl chains (independent, latencies overlap)
        #pragma unroll
        for (int o = 16; o > 0; o >>= 1) {
            Sp += __shfl_xor_sync(0xffffffffu, Sp, o);
            Qp += __shfl_xor_sync(0xffffffffu, Qp, o);
        }
        if (lane == 0) red_sq[blk & 1][wid] = make_float2(Sp, Qp);
        __syncthreads();
        // broadcast read of 8 (S,Q) partials as 4 float4; packed add keeps
        // S in lo lane and Q in hi lane of each u64 simultaneously.
        const float4* rs = reinterpret_cast<const float4*>(&red_sq[blk & 1][0]);
        float4 r0 = rs[0], r1 = rs[1], r2 = rs[2], r3 = rs[3];
        u64 t0 = add2(pk2(r0.x, r0.y), pk2(r0.z, r0.w));
        u64 t1 = add2(pk2(r1.x, r1.y), pk2(r1.z, r1.w));
        u64 t2 = add2(pk2(r2.x, r2.y), pk2(r2.z, r2.w));
        u64 t3 = add2(pk2(r3.x, r3.y), pk2(r3.z, r3.w));
        t0 = add2(add2(t0, t1), add2(t2, t3));
        float S, Q; upk2(t0, S, Q);
        float inv0 = rcpf(S);
        ninv0 = -inv0;
        float S1 = fmaf(Q, ninv0, S);    // S1 = S - Q/S (exact next-iter sum)
        ninv1 = -rcpf(S1);
    };

    #pragma unroll 1
    for (int blk = 0; blk < KITER / 2 - 1; blk++) {
        float ninv0, ninv1;
        block_ninv_pair(blk, ninv0, ninv1);
        u64 n0 = pk2(ninv0, ninv0);
        u64 n1 = pk2(ninv1, ninv1);
        #pragma unroll
        for (int p = 0; p < NPAIR; p++) {
            u64 noh = mul2(w2[p], n0);           // -onehot (iter A)
            w2[p]   = fma2(noh, w2[p], w2[p]);   // w *= (1 - onehot)
            kn2[p]  = add2(kn2[p], noh);
            u64 noh1 = mul2(w2[p], n1);          // -onehot (iter B)
            w2[p]    = fma2(noh1, w2[p], w2[p]);
            kn2[p]   = add2(kn2[p], noh1);
        }
    }
    {   // last block (iters 14,15): final w update is dead
        float ninv0, ninv1;
        block_ninv_pair(KITER / 2 - 1, ninv0, ninv1);
        u64 n0 = pk2(ninv0, ninv0);
        u64 n1 = pk2(ninv1, ninv1);
        #pragma unroll
        for (int p = 0; p < NPAIR; p++) {
            u64 noh = mul2(w2[p], n0);
            w2[p]   = fma2(noh, w2[p], w2[p]);
            kn2[p]  = add2(kn2[p], noh);
            u64 noh1 = mul2(w2[p], n1);
            kn2[p]   = add2(kn2[p], noh1);
        }
    }

    // ---- store khot = -kn (coalesced float4) ----
    float4* o4 = reinterpret_cast<float4*>(out + base);
    #pragma unroll
    for (int j = 0; j < 4; j++) {
        float4 v;
        float x0, x1, x2, x3;
        upk2(kn2[2*j],     x0, x1);
        upk2(kn2[2*j + 1], x2, x3);
        v.x = -x0; v.y = -x1; v.z = -x2; v.w = -x3;
        o4[j * TPB + tid] = v;
    }
}

extern "C" void kernel_launch(void* const* d_in, const int* in_sizes, int n_in,
                              void* d_out, int out_size) {
    const float* scores = (const float*)d_in[0];
    const float* g      = (const float*)d_in[1];
    float* out          = (float*)d_out;
    int rows = in_sizes[0] / NCOL;   // 4*2048 = 8192
    subset_op_kernel<<<rows, TPB>>>(scores, g, out);
}